// round 2
// baseline (speedup 1.0000x reference)
#include <cuda_runtime.h>
#include <cstdint>

typedef unsigned long long u64;

#define B_    256
#define T_    512
#define NPAIR 128

// ---- device scratch (no allocations allowed) ------------------------------
__device__ __align__(16) u64    g_seqA[(size_t)T_ * NPAIR * 64];   // 33.5 MB packed pairs
__device__ __align__(16) u64    g_seqB[(size_t)T_ * NPAIR * 64];   // 33.5 MB
__device__ __align__(16) u64    g_prebuf[(size_t)T_ * NPAIR * 256];// 134 MB  [slot][gate]
__device__ __align__(16) float4 g_pb0[(size_t)T_ * B_];            // 2 MB    [t][b]

// ---- packed f32x2 helpers -------------------------------------------------
__device__ __forceinline__ u64 pk2(float a, float b) {
    u64 r; asm("mov.b64 %0, {%1, %2};" : "=l"(r) : "f"(a), "f"(b)); return r;
}
__device__ __forceinline__ void unpk(u64 v, float& a, float& b) {
    asm("mov.b64 {%0, %1}, %2;" : "=f"(a), "=f"(b) : "l"(v));
}
__device__ __forceinline__ u64 ffma2(u64 a, u64 b, u64 c) {
    u64 d; asm("fma.rn.f32x2 %0, %1, %2, %3;" : "=l"(d) : "l"(a), "l"(b), "l"(c)); return d;
}
__device__ __forceinline__ u64 add2(u64 a, u64 b) {
    u64 d; asm("add.rn.f32x2 %0, %1, %2;" : "=l"(d) : "l"(a), "l"(b)); return d;
}

// ---- fast activations (MUFU ex2+rcp, ~1e-7 err) ---------------------------
#define L2E 1.4426950408889634f
__device__ __forceinline__ float ex2a(float x) {
    float r; asm("ex2.approx.ftz.f32 %0, %1;" : "=f"(r) : "f"(x)); return r;
}
__device__ __forceinline__ float rcpa(float x) {
    float r; asm("rcp.approx.ftz.f32 %0, %1;" : "=f"(r) : "f"(x)); return r;
}
__device__ __forceinline__ float sga(float x) { return rcpa(1.f + ex2a(-L2E * x)); }
__device__ __forceinline__ float tna(float x) {
    return fmaf(-2.f, rcpa(1.f + ex2a(2.f * L2E * x)), 1.f);
}

// ---------------------------------------------------------------------------
// H=64 LSTM recurrence. block = one batch pair, thread = one gate.
// MODE 0: Din=1 (layer a0), pre-gates inline from x. MODE 1: from g_prebuf.
// outsel: 0 -> g_seqA, 1 -> g_seqB (packed-pair layout [t*128+pair][d][2]).
// ---------------------------------------------------------------------------
template <int MODE>
__global__ __launch_bounds__(256, 1) void rec64(
    const float* __restrict__ w_hh, const float* __restrict__ xin,
    const float* __restrict__ w_ih, const float* __restrict__ b_ih,
    const float* __restrict__ b_hh, int outsel)
{
    __shared__ __align__(16) u64 h2s[64];
    __shared__ float2 gsm[256];
    __shared__ float  xs[2][T_];

    const int g = threadIdx.x;
    const int pair = blockIdx.x;
    float* outf = outsel ? reinterpret_cast<float*>(g_seqB)
                         : reinterpret_cast<float*>(g_seqA);

    u64 w2[64];
    const float* wr = w_hh + g * 64;
#pragma unroll
    for (int d = 0; d < 64; ++d) { float w = __ldg(wr + d); w2[d] = pk2(w, w); }

    u64 bias2 = 0ull, wih0 = 0ull;
    if (MODE == 0) {
        float bb = __ldg(b_ih + g) + __ldg(b_hh + g);
        bias2 = pk2(bb, bb);
        float wi = __ldg(w_ih + g);
        wih0 = pk2(wi, wi);
#pragma unroll
        for (int k = 0; k < 4; ++k) {
            int i = g + 256 * k, bl = i >> 9, t = i & 511;
            xs[bl][t] = xin[(size_t)(pair * 2 + bl) * T_ + t];
        }
    }
    if (g < 64) h2s[g] = 0ull;

    const bool istanh = (g >= 128 && g < 192);
    const float ca = istanh ? 2.f * L2E : -L2E;
    const float aa = istanh ? 1.f : 0.f;
    const float bm = istanh ? -2.f : 1.f;

    u64 pre0 = 0ull, pre1 = 0ull;
    if (MODE == 1) {
        pre0 = __ldg(g_prebuf + (size_t)(0 * NPAIR + pair) * 256 + g);
        pre1 = __ldg(g_prebuf + (size_t)(1 * NPAIR + pair) * 256 + g);
    }
    float c = 0.f;
    __syncthreads();

    for (int t = 0; t < T_; ++t) {
        u64 a0, a1 = 0ull, a2 = 0ull, a3 = 0ull;
        if (MODE == 0) {
            a0 = ffma2(wih0, pk2(xs[0][t], xs[1][t]), bias2);
        } else {
            a0 = pre0; pre0 = pre1;
            pre1 = (t + 2 < T_)
                 ? __ldg(g_prebuf + (size_t)((t + 2) * NPAIR + pair) * 256 + g)
                 : 0ull;
        }
        const ulonglong2* hp = reinterpret_cast<const ulonglong2*>(h2s);
#pragma unroll
        for (int d = 0; d < 64; d += 8) {
            ulonglong2 p0 = hp[(d >> 1) + 0], p1 = hp[(d >> 1) + 1];
            ulonglong2 p2 = hp[(d >> 1) + 2], p3 = hp[(d >> 1) + 3];
            a0 = ffma2(w2[d + 0], p0.x, a0); a1 = ffma2(w2[d + 1], p0.y, a1);
            a2 = ffma2(w2[d + 2], p1.x, a2); a3 = ffma2(w2[d + 3], p1.y, a3);
            a0 = ffma2(w2[d + 4], p2.x, a0); a1 = ffma2(w2[d + 5], p2.y, a1);
            a2 = ffma2(w2[d + 6], p3.x, a2); a3 = ffma2(w2[d + 7], p3.y, a3);
        }
        u64 s = add2(add2(a0, a1), add2(a2, a3));
        float va, vb; unpk(s, va, vb);
        float ra = fmaf(bm, rcpa(1.f + ex2a(ca * va)), aa);
        float rb = fmaf(bm, rcpa(1.f + ex2a(ca * vb)), aa);
        gsm[g] = make_float2(ra, rb);
        __syncthreads();

        if (g < 128) {
            int unit = g & 63, nb = g >> 6;
            float2 gi = gsm[unit], gf = gsm[unit + 64];
            float2 gg = gsm[unit + 128], go = gsm[unit + 192];
            float iv = nb ? gi.y : gi.x, fv = nb ? gf.y : gf.x;
            float gv = nb ? gg.y : gg.x, ov = nb ? go.y : go.x;
            c = fmaf(fv, c, iv * gv);
            float h = ov * tna(c);
            reinterpret_cast<float*>(h2s)[unit * 2 + nb] = h;
            outf[((size_t)(t * NPAIR + pair) * 64 + unit) * 2 + nb] = h;
        }
        __syncthreads();
    }
}

// ---------------------------------------------------------------------------
// Input projection GEMM for a1/a2: prebuf[slot][g] = bias + W_ih . x[slot]
// 1024 blocks x 256 threads; 64 slots/block in 4 chunks of 16, smem staged.
// ---------------------------------------------------------------------------
__global__ __launch_bounds__(256, 1) void inj64(
    int insel, const float* __restrict__ w_ih,
    const float* __restrict__ b_ih, const float* __restrict__ b_hh)
{
    __shared__ __align__(16) u64 xsm[16 * 64];
    const u64* xseq = insel ? g_seqB : g_seqA;
    const int g = threadIdx.x;

    u64 w2[64];
    const float* wr = w_ih + g * 64;
#pragma unroll
    for (int d = 0; d < 64; ++d) { float w = __ldg(wr + d); w2[d] = pk2(w, w); }
    float bb = __ldg(b_ih + g) + __ldg(b_hh + g);
    const u64 bias2 = pk2(bb, bb);
    const size_t slot0 = (size_t)blockIdx.x * 64;

    for (int ch = 0; ch < 4; ++ch) {
        __syncthreads();
        const u64* src = xseq + (slot0 + ch * 16) * 64;
#pragma unroll
        for (int k = 0; k < 4; ++k) xsm[k * 256 + g] = src[k * 256 + g];
        __syncthreads();
        for (int ls = 0; ls < 16; ++ls) {
            const ulonglong2* xp = reinterpret_cast<const ulonglong2*>(xsm + ls * 64);
            u64 a0 = bias2, a1 = 0ull, a2 = 0ull, a3 = 0ull;
#pragma unroll
            for (int j = 0; j < 32; j += 4) {
                ulonglong2 q0 = xp[j], q1 = xp[j + 1], q2 = xp[j + 2], q3 = xp[j + 3];
                a0 = ffma2(w2[2 * j + 0], q0.x, a0); a1 = ffma2(w2[2 * j + 1], q0.y, a1);
                a2 = ffma2(w2[2 * j + 2], q1.x, a2); a3 = ffma2(w2[2 * j + 3], q1.y, a3);
                a0 = ffma2(w2[2 * j + 4], q2.x, a0); a1 = ffma2(w2[2 * j + 5], q2.y, a1);
                a2 = ffma2(w2[2 * j + 6], q3.x, a2); a3 = ffma2(w2[2 * j + 7], q3.y, a3);
            }
            g_prebuf[(slot0 + ch * 16 + ls) * 256 + g] = add2(add2(a0, a1), add2(a2, a3));
        }
    }
}

// ---------------------------------------------------------------------------
// b0 pre-gates: g_pb0[t][b] = bias_b0 + W_ih_b0[4,64] . x[t][b]  (x = g_seqA)
// ---------------------------------------------------------------------------
__global__ __launch_bounds__(256, 1) void preb0(
    const float* __restrict__ w_ih, const float* __restrict__ b_ih,
    const float* __restrict__ b_hh)
{
    __shared__ u64 wsm[256];
    __shared__ float bsm[4];
    const int tid = threadIdx.x;
    { float w = __ldg(w_ih + tid); wsm[tid] = pk2(w, w); }
    if (tid < 4) bsm[tid] = __ldg(b_ih + tid) + __ldg(b_hh + tid);
    __syncthreads();

    const size_t slot = (size_t)blockIdx.x * 256 + tid;
    const u64* xp = g_seqA + slot * 64;
    u64 acc[4] = {0ull, 0ull, 0ull, 0ull};
    for (int d = 0; d < 64; ++d) {
        u64 x = __ldg(xp + d);
#pragma unroll
        for (int gg = 0; gg < 4; ++gg) acc[gg] = ffma2(wsm[gg * 64 + d], x, acc[gg]);
    }
    float lo[4], hi[4];
#pragma unroll
    for (int gg = 0; gg < 4; ++gg) unpk(acc[gg], lo[gg], hi[gg]);
    g_pb0[2 * slot + 0] = make_float4(lo[0] + bsm[0], lo[1] + bsm[1], lo[2] + bsm[2], lo[3] + bsm[3]);
    g_pb0[2 * slot + 1] = make_float4(hi[0] + bsm[0], hi[1] + bsm[1], hi[2] + bsm[2], hi[3] + bsm[3]);
}

// ---------------------------------------------------------------------------
// b0,b1,b2 scalar recurrences, layer-pipelined. 8 blocks x 32 threads.
// ---------------------------------------------------------------------------
__device__ __forceinline__ void step1(float4 pre, float4 whh, float& c, float& h) {
    float iv = sga(fmaf(whh.x, h, pre.x));
    float fv = sga(fmaf(whh.y, h, pre.y));
    float gv = tna(fmaf(whh.z, h, pre.z));
    float ov = sga(fmaf(whh.w, h, pre.w));
    c = fmaf(fv, c, iv * gv);
    h = ov * tna(c);
}

__global__ __launch_bounds__(32, 1) void b012(
    const float* __restrict__ whh0,
    const float* __restrict__ wih1, const float* __restrict__ whh1,
    const float* __restrict__ bih1, const float* __restrict__ bhh1,
    const float* __restrict__ wih2, const float* __restrict__ whh2,
    const float* __restrict__ bih2, const float* __restrict__ bhh2,
    float* __restrict__ out)
{
    const int b = blockIdx.x * 32 + threadIdx.x;
    float4 W0 = make_float4(whh0[0], whh0[1], whh0[2], whh0[3]);
    float4 I1 = make_float4(wih1[0], wih1[1], wih1[2], wih1[3]);
    float4 H1 = make_float4(whh1[0], whh1[1], whh1[2], whh1[3]);
    float4 B1 = make_float4(bih1[0] + bhh1[0], bih1[1] + bhh1[1],
                            bih1[2] + bhh1[2], bih1[3] + bhh1[3]);
    float4 I2 = make_float4(wih2[0], wih2[1], wih2[2], wih2[3]);
    float4 H2 = make_float4(whh2[0], whh2[1], whh2[2], whh2[3]);
    float4 B2 = make_float4(bih2[0] + bhh2[0], bih2[1] + bhh2[1],
                            bih2[2] + bhh2[2], bih2[3] + bhh2[3]);

    float c0 = 0.f, h0 = 0.f, c1 = 0.f, h1 = 0.f, c2 = 0.f, h2v = 0.f;
    float4 p0 = g_pb0[b];
    float4 p1 = g_pb0[256 + b];

    for (int tt = 0; tt < T_ + 2; ++tt) {
        float4 pn = (tt + 2 < T_) ? g_pb0[(size_t)(tt + 2) * 256 + b]
                                  : make_float4(0.f, 0.f, 0.f, 0.f);
        float in0 = h0, in1 = h1;
        if (tt < T_) step1(p0, W0, c0, h0);
        if (tt >= 1 && tt < T_ + 1) {
            float4 pre = make_float4(fmaf(I1.x, in0, B1.x), fmaf(I1.y, in0, B1.y),
                                     fmaf(I1.z, in0, B1.z), fmaf(I1.w, in0, B1.w));
            step1(pre, H1, c1, h1);
        }
        if (tt >= 2) {
            float4 pre = make_float4(fmaf(I2.x, in1, B2.x), fmaf(I2.y, in1, B2.y),
                                     fmaf(I2.z, in1, B2.z), fmaf(I2.w, in1, B2.w));
            step1(pre, H2, c2, h2v);
            out[(size_t)b * T_ + (tt - 2)] = h2v;
        }
        p0 = p1; p1 = pn;
    }
}

// ---------------------------------------------------------------------------
extern "C" void kernel_launch(void* const* d_in, const int* in_sizes, int n_in,
                              void* d_out, int out_size)
{
    const float* x = (const float*)d_in[0];
#define LAYER(i) (const float*)d_in[1+4*(i)], (const float*)d_in[2+4*(i)], \
                 (const float*)d_in[3+4*(i)], (const float*)d_in[4+4*(i)]
    // layer i: w_ih, w_hh, b_ih, b_hh
    const float *wih_a0, *whh_a0, *bih_a0, *bhh_a0;
    const float *wih_a1, *whh_a1, *bih_a1, *bhh_a1;
    const float *wih_a2, *whh_a2, *bih_a2, *bhh_a2;
    const float *wih_b0, *whh_b0, *bih_b0, *bhh_b0;
    const float *wih_b1, *whh_b1, *bih_b1, *bhh_b1;
    const float *wih_b2, *whh_b2, *bih_b2, *bhh_b2;
    wih_a0 = (const float*)d_in[1];  whh_a0 = (const float*)d_in[2];
    bih_a0 = (const float*)d_in[3];  bhh_a0 = (const float*)d_in[4];
    wih_a1 = (const float*)d_in[5];  whh_a1 = (const float*)d_in[6];
    bih_a1 = (const float*)d_in[7];  bhh_a1 = (const float*)d_in[8];
    wih_a2 = (const float*)d_in[9];  whh_a2 = (const float*)d_in[10];
    bih_a2 = (const float*)d_in[11]; bhh_a2 = (const float*)d_in[12];
    wih_b0 = (const float*)d_in[13]; whh_b0 = (const float*)d_in[14];
    bih_b0 = (const float*)d_in[15]; bhh_b0 = (const float*)d_in[16];
    wih_b1 = (const float*)d_in[17]; whh_b1 = (const float*)d_in[18];
    bih_b1 = (const float*)d_in[19]; bhh_b1 = (const float*)d_in[20];
    wih_b2 = (const float*)d_in[21]; whh_b2 = (const float*)d_in[22];
    bih_b2 = (const float*)d_in[23]; bhh_b2 = (const float*)d_in[24];
    float* out = (float*)d_out;

    // a0: Din=1 recurrence -> seqA
    rec64<0><<<NPAIR, 256>>>(whh_a0, x, wih_a0, bih_a0, bhh_a0, 0);
    // a1: inj from seqA -> prebuf; recurrence -> seqB
    inj64<<<1024, 256>>>(0, wih_a1, bih_a1, bhh_a1);
    rec64<1><<<NPAIR, 256>>>(whh_a1, nullptr, nullptr, nullptr, nullptr, 1);
    // a2: inj from seqB -> prebuf; recurrence -> seqA
    inj64<<<1024, 256>>>(1, wih_a2, bih_a2, bhh_a2);
    rec64<1><<<NPAIR, 256>>>(whh_a2, nullptr, nullptr, nullptr, nullptr, 0);
    // b0 pre-gates from seqA
    preb0<<<256, 256>>>(wih_b0, bih_b0, bhh_b0);
    // b0/b1/b2 fused scalar recurrences -> out
    b012<<<8, 32>>>(whh_b0, wih_b1, whh_b1, bih_b1, bhh_b1,
                    wih_b2, whh_b2, bih_b2, bhh_b2, out);
}

// round 3
// speedup vs baseline: 1.0645x; 1.0645x over previous
#include <cuda_runtime.h>
#include <cstdint>

typedef unsigned long long u64;

#define B_    256
#define T_    512
#define NPAIR 128

// ---- device scratch (no allocations allowed) ------------------------------
// seq layout: [t][b][64] plain floats
__device__ __align__(16) float  g_seqA[(size_t)T_ * B_ * 64];      // 33.5 MB
__device__ __align__(16) float  g_seqB[(size_t)T_ * B_ * 64];      // 33.5 MB
__device__ __align__(16) u64    g_prebuf[(size_t)T_ * NPAIR * 256];// 134 MB [t*128+pair][gate] -> (b0,b1)
__device__ __align__(16) float4 g_pb0[(size_t)T_ * B_];            // 2 MB   [t*256+b]

// ---- packed f32x2 helpers -------------------------------------------------
__device__ __forceinline__ u64 pk2(float a, float b) {
    u64 r; asm("mov.b64 %0, {%1, %2};" : "=l"(r) : "f"(a), "f"(b)); return r;
}
__device__ __forceinline__ void unpk(u64 v, float& a, float& b) {
    asm("mov.b64 {%0, %1}, %2;" : "=f"(a), "=f"(b) : "l"(v));
}
__device__ __forceinline__ u64 ffma2(u64 a, u64 b, u64 c) {
    u64 d; asm("fma.rn.f32x2 %0, %1, %2, %3;" : "=l"(d) : "l"(a), "l"(b), "l"(c)); return d;
}
__device__ __forceinline__ u64 add2(u64 a, u64 b) {
    u64 d; asm("add.rn.f32x2 %0, %1, %2;" : "=l"(d) : "l"(a), "l"(b)); return d;
}

// ---- fast activations (MUFU ex2+rcp, ~1e-7 err) ---------------------------
#define L2E 1.4426950408889634f
__device__ __forceinline__ float ex2a(float x) {
    float r; asm("ex2.approx.ftz.f32 %0, %1;" : "=f"(r) : "f"(x)); return r;
}
__device__ __forceinline__ float rcpa(float x) {
    float r; asm("rcp.approx.ftz.f32 %0, %1;" : "=f"(r) : "f"(x)); return r;
}
__device__ __forceinline__ float sga(float x) { return rcpa(1.f + ex2a(-L2E * x)); }
__device__ __forceinline__ float tna(float x) {
    return fmaf(-2.f, rcpa(1.f + ex2a(2.f * L2E * x)), 1.f);
}

// ---------------------------------------------------------------------------
// H=64 LSTM recurrence. block = one batch pair, thread = one gate.
// MODE 0: Din=1 (layer a0), pre-gates inline from x. MODE 1: from g_prebuf.
// Output: [t][b][64] floats into g_seqA (outsel=0) or g_seqB (outsel=1).
// ---------------------------------------------------------------------------
template <int MODE>
__global__ __launch_bounds__(256, 1) void rec64(
    const float* __restrict__ w_hh, const float* __restrict__ xin,
    const float* __restrict__ w_ih, const float* __restrict__ b_ih,
    const float* __restrict__ b_hh, int outsel)
{
    __shared__ __align__(16) u64 h2s[64];
    __shared__ float2 gsm[256];
    __shared__ float  xs[2][T_];

    const int g = threadIdx.x;
    const int pair = blockIdx.x;
    float* outf = outsel ? g_seqB : g_seqA;

    u64 w2[64];
    const float* wr = w_hh + g * 64;
#pragma unroll
    for (int d = 0; d < 64; ++d) { float w = __ldg(wr + d); w2[d] = pk2(w, w); }

    u64 bias2 = 0ull, wih0 = 0ull;
    if (MODE == 0) {
        float bb = __ldg(b_ih + g) + __ldg(b_hh + g);
        bias2 = pk2(bb, bb);
        float wi = __ldg(w_ih + g);
        wih0 = pk2(wi, wi);
#pragma unroll
        for (int k = 0; k < 4; ++k) {
            int i = g + 256 * k, bl = i >> 9, t = i & 511;
            xs[bl][t] = xin[(size_t)(pair * 2 + bl) * T_ + t];
        }
    }
    if (g < 64) h2s[g] = 0ull;

    const bool istanh = (g >= 128 && g < 192);
    const float ca = istanh ? 2.f * L2E : -L2E;
    const float aa = istanh ? 1.f : 0.f;
    const float bm = istanh ? -2.f : 1.f;

    u64 pre0 = 0ull, pre1 = 0ull;
    if (MODE == 1) {
        pre0 = __ldg(g_prebuf + (size_t)(0 * NPAIR + pair) * 256 + g);
        pre1 = __ldg(g_prebuf + (size_t)(1 * NPAIR + pair) * 256 + g);
    }
    float c = 0.f;
    __syncthreads();

    for (int t = 0; t < T_; ++t) {
        u64 a0, a1 = 0ull, a2 = 0ull, a3 = 0ull;
        if (MODE == 0) {
            a0 = ffma2(wih0, pk2(xs[0][t], xs[1][t]), bias2);
        } else {
            a0 = pre0; pre0 = pre1;
            pre1 = (t + 2 < T_)
                 ? __ldg(g_prebuf + (size_t)((t + 2) * NPAIR + pair) * 256 + g)
                 : 0ull;
        }
        const ulonglong2* hp = reinterpret_cast<const ulonglong2*>(h2s);
#pragma unroll
        for (int d = 0; d < 64; d += 8) {
            ulonglong2 p0 = hp[(d >> 1) + 0], p1 = hp[(d >> 1) + 1];
            ulonglong2 p2 = hp[(d >> 1) + 2], p3 = hp[(d >> 1) + 3];
            a0 = ffma2(w2[d + 0], p0.x, a0); a1 = ffma2(w2[d + 1], p0.y, a1);
            a2 = ffma2(w2[d + 2], p1.x, a2); a3 = ffma2(w2[d + 3], p1.y, a3);
            a0 = ffma2(w2[d + 4], p2.x, a0); a1 = ffma2(w2[d + 5], p2.y, a1);
            a2 = ffma2(w2[d + 6], p3.x, a2); a3 = ffma2(w2[d + 7], p3.y, a3);
        }
        u64 s = add2(add2(a0, a1), add2(a2, a3));
        float va, vb; unpk(s, va, vb);
        float ra = fmaf(bm, rcpa(1.f + ex2a(ca * va)), aa);
        float rb = fmaf(bm, rcpa(1.f + ex2a(ca * vb)), aa);
        gsm[g] = make_float2(ra, rb);
        __syncthreads();

        if (g < 128) {
            int unit = g & 63, nb = g >> 6;
            float2 gi = gsm[unit], gf = gsm[unit + 64];
            float2 gg = gsm[unit + 128], go = gsm[unit + 192];
            float iv = nb ? gi.y : gi.x, fv = nb ? gf.y : gf.x;
            float gv = nb ? gg.y : gg.x, ov = nb ? go.y : go.x;
            c = fmaf(fv, c, iv * gv);
            float h = ov * tna(c);
            reinterpret_cast<float*>(h2s)[unit * 2 + nb] = h;
            outf[((size_t)t * B_ + pair * 2 + nb) * 64 + unit] = h;
        }
        __syncthreads();
    }
}

// ---------------------------------------------------------------------------
// Input projection GEMM (dim-packed weights, 64 regs): for pair-slot s,
//   prebuf[s][g] = ( bias + w_ih[g].x[t][2p],  bias + w_ih[g].x[t][2p+1] )
// 1024 blocks x 256 threads, 2 blocks/SM. Block handles 64 pair-slots in
// 8 tiles of 8 (smem double-buffered; tile = 1024 contiguous floats).
// ---------------------------------------------------------------------------
__global__ __launch_bounds__(256, 2) void inj64(
    int insel, const float* __restrict__ w_ih,
    const float* __restrict__ b_ih, const float* __restrict__ b_hh)
{
    __shared__ __align__(16) float xsm[2][8 * 128];   // 8 KB
    const float* xseq = insel ? g_seqB : g_seqA;
    const int g = threadIdx.x;

    // w row as 32 dim-pair u64s: (w[2j], w[2j+1]) -- direct u64 load, no pack
    u64 w2[32];
    const u64* wrow = reinterpret_cast<const u64*>(w_ih) + (size_t)g * 32;
#pragma unroll
    for (int j = 0; j < 32; ++j) w2[j] = __ldg(wrow + j);
    const float bb = __ldg(b_ih + g) + __ldg(b_hh + g);

    const size_t s0 = (size_t)blockIdx.x * 64;                 // pair-slot base
    const float4* src = reinterpret_cast<const float4*>(xseq) + s0 * 32;

    // prologue: stage tile 0
    {
        float4 v = __ldg(src + g);
        reinterpret_cast<float4*>(xsm[0])[g] = v;
    }
    __syncthreads();

    for (int tl = 0; tl < 8; ++tl) {
        const int buf = tl & 1;
        float4 nxt;
        if (tl + 1 < 8) nxt = __ldg(src + (size_t)(tl + 1) * 256 + g);

#pragma unroll 2
        for (int sl = 0; sl < 8; ++sl) {
            const ulonglong2* x0 = reinterpret_cast<const ulonglong2*>(xsm[buf] + sl * 128);
            const ulonglong2* x1 = x0 + 16;
            u64 a0 = 0ull, a1 = 0ull, c0 = 0ull, c1 = 0ull;
#pragma unroll
            for (int j = 0; j < 16; ++j) {
                ulonglong2 q0 = x0[j];
                ulonglong2 q1 = x1[j];
                a0 = ffma2(w2[2 * j + 0], q0.x, a0);
                a1 = ffma2(w2[2 * j + 1], q0.y, a1);
                c0 = ffma2(w2[2 * j + 0], q1.x, c0);
                c1 = ffma2(w2[2 * j + 1], q1.y, c1);
            }
            u64 sa = add2(a0, a1), sc = add2(c0, c1);
            float ea, oa, ec, oc;
            unpk(sa, ea, oa); unpk(sc, ec, oc);
            g_prebuf[(s0 + (size_t)tl * 8 + sl) * 256 + g] = pk2(ea + oa + bb, ec + oc + bb);
        }

        if (tl + 1 < 8) {
            reinterpret_cast<float4*>(xsm[buf ^ 1])[g] = nxt;
            __syncthreads();
        }
    }
}

// ---------------------------------------------------------------------------
// b0 pre-gates: g_pb0[t*256+b] = bias_b0 + W_ih_b0[4,64] . seqA[t][b]
// dim-packed weights in smem; thread per batch-slot. 512 blocks x 256.
// ---------------------------------------------------------------------------
__global__ __launch_bounds__(256, 1) void preb0(
    const float* __restrict__ w_ih, const float* __restrict__ b_ih,
    const float* __restrict__ b_hh)
{
    __shared__ u64 wsm[128];          // 4 gates x 32 dim-pairs
    __shared__ float bsm[4];
    const int tid = threadIdx.x;
    if (tid < 128) wsm[tid] = __ldg(reinterpret_cast<const u64*>(w_ih) + tid);
    if (tid < 4) bsm[tid] = __ldg(b_ih + tid) + __ldg(b_hh + tid);
    __syncthreads();

    const size_t slot = (size_t)blockIdx.x * 256 + tid;        // = t*256 + b
    const u64* xp = reinterpret_cast<const u64*>(g_seqA) + slot * 32;
    u64 acc[4] = {0ull, 0ull, 0ull, 0ull};
#pragma unroll 8
    for (int j = 0; j < 32; ++j) {
        u64 xv = __ldg(xp + j);
#pragma unroll
        for (int gg = 0; gg < 4; ++gg)
            acc[gg] = ffma2(wsm[gg * 32 + j], xv, acc[gg]);
    }
    float r[4];
#pragma unroll
    for (int gg = 0; gg < 4; ++gg) {
        float e, o; unpk(acc[gg], e, o);
        r[gg] = e + o + bsm[gg];
    }
    g_pb0[slot] = make_float4(r[0], r[1], r[2], r[3]);
}

// ---------------------------------------------------------------------------
// b0,b1,b2 scalar recurrences, layer-pipelined. 8 blocks x 32 threads.
// ---------------------------------------------------------------------------
__device__ __forceinline__ void step1(float4 pre, float4 whh, float& c, float& h) {
    float iv = sga(fmaf(whh.x, h, pre.x));
    float fv = sga(fmaf(whh.y, h, pre.y));
    float gv = tna(fmaf(whh.z, h, pre.z));
    float ov = sga(fmaf(whh.w, h, pre.w));
    c = fmaf(fv, c, iv * gv);
    h = ov * tna(c);
}

__global__ __launch_bounds__(32, 1) void b012(
    const float* __restrict__ whh0,
    const float* __restrict__ wih1, const float* __restrict__ whh1,
    const float* __restrict__ bih1, const float* __restrict__ bhh1,
    const float* __restrict__ wih2, const float* __restrict__ whh2,
    const float* __restrict__ bih2, const float* __restrict__ bhh2,
    float* __restrict__ out)
{
    const int b = blockIdx.x * 32 + threadIdx.x;
    float4 W0 = make_float4(whh0[0], whh0[1], whh0[2], whh0[3]);
    float4 I1 = make_float4(wih1[0], wih1[1], wih1[2], wih1[3]);
    float4 H1 = make_float4(whh1[0], whh1[1], whh1[2], whh1[3]);
    float4 B1 = make_float4(bih1[0] + bhh1[0], bih1[1] + bhh1[1],
                            bih1[2] + bhh1[2], bih1[3] + bhh1[3]);
    float4 I2 = make_float4(wih2[0], wih2[1], wih2[2], wih2[3]);
    float4 H2 = make_float4(whh2[0], whh2[1], whh2[2], whh2[3]);
    float4 B2 = make_float4(bih2[0] + bhh2[0], bih2[1] + bhh2[1],
                            bih2[2] + bhh2[2], bih2[3] + bhh2[3]);

    float c0 = 0.f, h0 = 0.f, c1 = 0.f, h1 = 0.f, c2 = 0.f, h2v = 0.f;
    float4 p0 = g_pb0[b];
    float4 p1 = g_pb0[256 + b];

    for (int tt = 0; tt < T_ + 2; ++tt) {
        float4 pn = (tt + 2 < T_) ? g_pb0[(size_t)(tt + 2) * 256 + b]
                                  : make_float4(0.f, 0.f, 0.f, 0.f);
        float in0 = h0, in1 = h1;
        if (tt < T_) step1(p0, W0, c0, h0);
        if (tt >= 1 && tt < T_ + 1) {
            float4 pre = make_float4(fmaf(I1.x, in0, B1.x), fmaf(I1.y, in0, B1.y),
                                     fmaf(I1.z, in0, B1.z), fmaf(I1.w, in0, B1.w));
            step1(pre, H1, c1, h1);
        }
        if (tt >= 2) {
            float4 pre = make_float4(fmaf(I2.x, in1, B2.x), fmaf(I2.y, in1, B2.y),
                                     fmaf(I2.z, in1, B2.z), fmaf(I2.w, in1, B2.w));
            step1(pre, H2, c2, h2v);
            out[(size_t)b * T_ + (tt - 2)] = h2v;
        }
        p0 = p1; p1 = pn;
    }
}

// ---------------------------------------------------------------------------
extern "C" void kernel_launch(void* const* d_in, const int* in_sizes, int n_in,
                              void* d_out, int out_size)
{
    const float* x = (const float*)d_in[0];
    const float *wih_a0 = (const float*)d_in[1],  *whh_a0 = (const float*)d_in[2];
    const float *bih_a0 = (const float*)d_in[3],  *bhh_a0 = (const float*)d_in[4];
    const float *wih_a1 = (const float*)d_in[5],  *whh_a1 = (const float*)d_in[6];
    const float *bih_a1 = (const float*)d_in[7],  *bhh_a1 = (const float*)d_in[8];
    const float *wih_a2 = (const float*)d_in[9],  *whh_a2 = (const float*)d_in[10];
    const float *bih_a2 = (const float*)d_in[11], *bhh_a2 = (const float*)d_in[12];
    const float *wih_b0 = (const float*)d_in[13], *whh_b0 = (const float*)d_in[14];
    const float *bih_b0 = (const float*)d_in[15], *bhh_b0 = (const float*)d_in[16];
    const float *wih_b1 = (const float*)d_in[17], *whh_b1 = (const float*)d_in[18];
    const float *bih_b1 = (const float*)d_in[19], *bhh_b1 = (const float*)d_in[20];
    const float *wih_b2 = (const float*)d_in[21], *whh_b2 = (const float*)d_in[22];
    const float *bih_b2 = (const float*)d_in[23], *bhh_b2 = (const float*)d_in[24];
    float* out = (float*)d_out;

    // a0: Din=1 recurrence -> seqA
    rec64<0><<<NPAIR, 256>>>(whh_a0, x, wih_a0, bih_a0, bhh_a0, 0);
    // a1: inj from seqA -> prebuf; recurrence -> seqB
    inj64<<<1024, 256>>>(0, wih_a1, bih_a1, bhh_a1);
    rec64<1><<<NPAIR, 256>>>(whh_a1, nullptr, nullptr, nullptr, nullptr, 1);
    // a2: inj from seqB -> prebuf; recurrence -> seqA
    inj64<<<1024, 256>>>(1, wih_a2, bih_a2, bhh_a2);
    rec64<1><<<NPAIR, 256>>>(whh_a2, nullptr, nullptr, nullptr, nullptr, 0);
    // b0 pre-gates from seqA
    preb0<<<512, 256>>>(wih_b0, bih_b0, bhh_b0);
    // b0/b1/b2 fused scalar recurrences -> out
    b012<<<8, 32>>>(whh_b0, wih_b1, whh_b1, bih_b1, bhh_b1,
                    wih_b2, whh_b2, bih_b2, bhh_b2, out);
}